// round 14
// baseline (speedup 1.0000x reference)
#include <cuda_runtime.h>
#include <cstdint>

#define HIDDEN 2048
#define HEADS 16
#define HEAD_DIM 128
#define BATCH 2
#define SEQ 2048
#define MROWS (BATCH * SEQ)  // 4096

// ---------------- scratch (no allocations allowed) ----------------
__device__ float g_q[MROWS * HIDDEN];     // 32 MB
__device__ float g_k[MROWS * HEAD_DIM];   // 2 MB
__device__ float g_v[MROWS * HEAD_DIM];   // 2 MB
__device__ float g_att[MROWS * HIDDEN];   // 32 MB

__device__ __forceinline__ uint32_t f2tf32(float x) {
    uint32_t r;
    asm("cvt.rna.tf32.f32 %0, %1;" : "=r"(r) : "f"(x));
    return r;
}
__device__ __forceinline__ float f2tf32f(float x) {
    return __uint_as_float(f2tf32(x));
}

#define MMA_TF32(d, a, b)                                                          \
    asm volatile(                                                                  \
        "mma.sync.aligned.m16n8k8.row.col.f32.tf32.tf32.f32 "                      \
        "{%0,%1,%2,%3}, {%4,%5,%6,%7}, {%8,%9}, {%0,%1,%2,%3};"                    \
        : "+f"((d)[0]), "+f"((d)[1]), "+f"((d)[2]), "+f"((d)[3])                   \
        : "r"((a)[0]), "r"((a)[1]), "r"((a)[2]), "r"((a)[3]),                      \
          "r"((b)[0]), "r"((b)[1]))

// ---------------- shared GEMM tile params ----------------
#define BM 128
#define BN 128
#define BK 32
#define SA 36
#define BUF_WORDS (BM * SA)
#define G_SMEM (2 * 2 * BUF_WORDS * 4)

// ---- core tf32 GEMM body: C[M,N] = A[M,K] @ B[N,K]^T (tile at m0,n0) ----
__device__ __forceinline__ void gemm_body(const float* __restrict__ A,
                                          const float* __restrict__ B,
                                          float* __restrict__ C,
                                          int K, int Cn, int m0, int n0,
                                          float* sm) {
    const int tid = threadIdx.x;
    const int w = tid >> 5;
    const int lane = tid & 31;
    const int g = lane >> 2;
    const int tg = lane & 3;
    const int warp_m = (w & 3) * 32;
    const int warp_n = (w >> 2) * 64;

    float acc[2][8][4];
#pragma unroll
    for (int t = 0; t < 2; t++)
#pragma unroll
        for (int u = 0; u < 8; u++)
#pragma unroll
            for (int j = 0; j < 4; j++) acc[t][u][j] = 0.0f;

    const int steps = K / BK;
    const int r_ld = tid >> 3;
    const int c_ld = (tid & 7) * 4;

    float4 afr[4], bfr[4];

    auto ldg = [&](int s) {
        const int k0 = s * BK;
#pragma unroll
        for (int i = 0; i < 4; i++) {
            int r = r_ld + i * 32;
            afr[i] = *(const float4*)(A + (size_t)(m0 + r) * K + k0 + c_ld);
            bfr[i] = *(const float4*)(B + (size_t)(n0 + r) * K + k0 + c_ld);
        }
    };
    auto sts = [&](int buf) {
        float* As = sm + buf * (2 * BUF_WORDS);
        float* Bs = As + BUF_WORDS;
#pragma unroll
        for (int i = 0; i < 4; i++) {
            int r = r_ld + i * 32;
            uint4 u;
            u.x = f2tf32(afr[i].x); u.y = f2tf32(afr[i].y);
            u.z = f2tf32(afr[i].z); u.w = f2tf32(afr[i].w);
            *(uint4*)(As + r * SA + c_ld) = u;
            u.x = f2tf32(bfr[i].x); u.y = f2tf32(bfr[i].y);
            u.z = f2tf32(bfr[i].z); u.w = f2tf32(bfr[i].w);
            *(uint4*)(Bs + r * SA + c_ld) = u;
        }
    };
    auto compute = [&](int buf) {
        const uint32_t* As = (const uint32_t*)(sm + buf * (2 * BUF_WORDS));
        const uint32_t* Bs = As + BUF_WORDS;
#pragma unroll
        for (int ks = 0; ks < 4; ks++) {
            const int kc = ks * 8 + tg;
            uint32_t a[2][4];
#pragma unroll
            for (int t = 0; t < 2; t++) {
                int row = warp_m + t * 16 + g;
                a[t][0] = As[row * SA + kc];
                a[t][1] = As[(row + 8) * SA + kc];
                a[t][2] = As[row * SA + kc + 4];
                a[t][3] = As[(row + 8) * SA + kc + 4];
            }
            uint32_t b[8][2];
#pragma unroll
            for (int u = 0; u < 8; u++) {
                int row = warp_n + u * 8 + g;
                b[u][0] = Bs[row * SA + kc];
                b[u][1] = Bs[row * SA + kc + 4];
            }
#pragma unroll
            for (int t = 0; t < 2; t++)
#pragma unroll
                for (int u = 0; u < 8; u++)
                    MMA_TF32(acc[t][u], a[t], b[u]);
        }
    };

    ldg(0);
    sts(0);
    __syncthreads();

    for (int s = 0; s < steps; s++) {
        const int cur = s & 1;
        if (s + 1 < steps) ldg(s + 1);
        compute(cur);
        if (s + 1 < steps) sts(cur ^ 1);
        __syncthreads();
    }

#pragma unroll
    for (int t = 0; t < 2; t++) {
        int r0 = m0 + warp_m + t * 16 + g;
#pragma unroll
        for (int u = 0; u < 8; u++) {
            int col = n0 + warp_n + u * 8 + 2 * tg;
            *(float2*)(C + (size_t)r0 * Cn + col) = make_float2(acc[t][u][0], acc[t][u][1]);
            *(float2*)(C + (size_t)(r0 + 8) * Cn + col) = make_float2(acc[t][u][2], acc[t][u][3]);
        }
    }
}

// out-projection GEMM (generic)
__global__ void __launch_bounds__(256) gemm_mma(const float* __restrict__ A,
                                                const float* __restrict__ B,
                                                float* __restrict__ C,
                                                int M, int N, int K) {
    extern __shared__ float sm[];
    gemm_body(A, B, C, K, N, blockIdx.y * BM, blockIdx.x * BN, sm);
}

// fused Q/K/V projection: grid.x 0..15 -> wq tiles, 16 -> wk, 17 -> wv
__global__ void __launch_bounds__(256) gemm_qkv(const float* __restrict__ x,
                                                const float* __restrict__ wq,
                                                const float* __restrict__ wk,
                                                const float* __restrict__ wv,
                                                float* __restrict__ qo,
                                                float* __restrict__ ko,
                                                float* __restrict__ vo) {
    extern __shared__ float sm[];
    const int bx = blockIdx.x;
    const float* B;
    float* C;
    int Cn, n0;
    if (bx < 16)      { B = wq; C = qo; Cn = HIDDEN;   n0 = bx * BN; }
    else if (bx == 16){ B = wk; C = ko; Cn = HEAD_DIM; n0 = 0; }
    else              { B = wv; C = vo; Cn = HEAD_DIM; n0 = 0; }
    gemm_body(x, B, C, HIDDEN, Cn, blockIdx.y * BM, n0, sm);
}

// ---------------- Flash attention v6: 1024 threads, 32 warps, occ 50% ----------------
// 128q/CTA, 64-key tiles. Warp grid 8(wm) x 4(wn).
// QK: warp = 16x16 of S (2 n-tiles). PV: warp = 16x32 of O (o[4][4] -> low regs).
// Register softmax with 4-segment cross-warp partials.
#define QTILE 128
#define QS_ST 132
#define KS_ST 132
#define VS_ST 136
#define SS_ST 68
#define OFF_QS 0
#define OFF_KS (QTILE * QS_ST)                  // 16896
#define OFF_VS (OFF_KS + 64 * KS_ST)            // 25344
#define OFF_SS (OFF_VS + 64 * VS_ST)            // 34048
#define OFF_M  (OFF_SS + QTILE * SS_ST)         // 42752
#define OFF_L  (OFF_M + QTILE)
#define OFF_F  (OFF_L + QTILE)
#define OFF_MN (OFF_F + QTILE)
#define OFF_PM (OFF_MN + QTILE)                 // [4][128]
#define OFF_PS (OFF_PM + 4 * QTILE)             // [4][128]
#define A_SMEM ((OFF_PS + 4 * QTILE) * 4)       // 177152 bytes

__global__ void __launch_bounds__(1024, 1) attn_kernel(const float* __restrict__ Q,
                                                       const float* __restrict__ Km,
                                                       const float* __restrict__ Vm,
                                                       float* __restrict__ O) {
    const int b = blockIdx.z;
    const int h = blockIdx.y;
    const int q0 = blockIdx.x * QTILE;

    extern __shared__ float sm[];
    float* qs   = sm + OFF_QS;
    float* ks   = sm + OFF_KS;
    float* vs   = sm + OFF_VS;
    float* ss   = sm + OFF_SS;
    float* m_s  = sm + OFF_M;
    float* l_s  = sm + OFF_L;
    float* f_s  = sm + OFF_F;
    float* mn_s = sm + OFF_MN;
    float* pm   = sm + OFF_PM;
    float* ps   = sm + OFF_PS;

    const int tid = threadIdx.x;
    const int w = tid >> 5;
    const int lane = tid & 31;
    const int g = lane >> 2;
    const int tg = lane & 3;
    const int wm = w & 7;          // 0..7: rows wm*16..+15
    const int wn = w >> 3;         // 0..3
    const float inv_norm = 0.08838834764831845f;  // 1/sqrt(128)

    const int r_st = tid >> 5;     // 0..31
    const int c_st = lane * 4;     // float col 0..124
    const int r0 = wm * 16 + g;
    const int r1 = r0 + 8;

    // ---- stage Q (128x128, tf32, stride 132) ----
    {
        const float* qbase = Q + (size_t)(b * SEQ + q0) * HIDDEN + h * HEAD_DIM;
#pragma unroll
        for (int it = 0; it < 4; it++) {
            int r = r_st + it * 32;
            float4 v = *(const float4*)(qbase + (size_t)r * HIDDEN + c_st);
            float* d = qs + r * QS_ST + c_st;
            d[0] = f2tf32f(v.x); d[1] = f2tf32f(v.y);
            d[2] = f2tf32f(v.z); d[3] = f2tf32f(v.w);
        }
    }
    if (tid < QTILE) {
        m_s[tid] = -3.0e38f;
        l_s[tid] = 0.0f;
    }

    float o[4][4];
#pragma unroll
    for (int u = 0; u < 4; u++)
#pragma unroll
        for (int j = 0; j < 4; j++) o[u][j] = 0.0f;

    __syncthreads();

    for (int t0 = 0; t0 < SEQ; t0 += 64) {
        // ---- stage K (stride 132) and V (stride 136), tf32 ----
        {
            const float* kbase = Km + (size_t)(b * SEQ + t0) * HEAD_DIM;
            const float* vbase = Vm + (size_t)(b * SEQ + t0) * HEAD_DIM;
#pragma unroll
            for (int it = 0; it < 2; it++) {
                int r = r_st + it * 32;
                float4 kv = *(const float4*)(kbase + (size_t)r * HEAD_DIM + c_st);
                float* dk = ks + r * KS_ST + c_st;
                dk[0] = f2tf32f(kv.x); dk[1] = f2tf32f(kv.y);
                dk[2] = f2tf32f(kv.z); dk[3] = f2tf32f(kv.w);
                float4 vv = *(const float4*)(vbase + (size_t)r * HEAD_DIM + c_st);
                float* dv = vs + r * VS_ST + c_st;
                dv[0] = f2tf32f(vv.x); dv[1] = f2tf32f(vv.y);
                dv[2] = f2tf32f(vv.z); dv[3] = f2tf32f(vv.w);
            }
        }
        __syncthreads();

        // ---- QK^T: warp computes S[wm*16..+15][wn*16..+15] (regs) ----
        float s[2][4];
#pragma unroll
        for (int u = 0; u < 2; u++)
#pragma unroll
            for (int j = 0; j < 4; j++) s[u][j] = 0.0f;
        {
            const uint32_t* qsu = (const uint32_t*)qs;
            const uint32_t* ksu = (const uint32_t*)ks;
            const int ncol0 = wn * 16;
#pragma unroll
            for (int kb = 0; kb < 16; kb++) {
                const int kc = kb * 8 + tg;
                uint32_t a[4];
                a[0] = qsu[r0 * QS_ST + kc];
                a[1] = qsu[r1 * QS_ST + kc];
                a[2] = qsu[r0 * QS_ST + kc + 4];
                a[3] = qsu[r1 * QS_ST + kc + 4];
#pragma unroll
                for (int u = 0; u < 2; u++) {
                    uint32_t bfr2[2];
                    int krow = ncol0 + u * 8 + g;
                    bfr2[0] = ksu[krow * KS_ST + kc];
                    bfr2[1] = ksu[krow * KS_ST + kc + 4];
                    MMA_TF32(s[u], a, bfr2);
                }
            }
        }

        // ---- register softmax, phase A: scale + partial row max (quad) ----
        {
            float pmax0 = -3.0e38f, pmax1 = -3.0e38f;
#pragma unroll
            for (int u = 0; u < 2; u++) {
                s[u][0] *= inv_norm; s[u][1] *= inv_norm;
                s[u][2] *= inv_norm; s[u][3] *= inv_norm;
                pmax0 = fmaxf(pmax0, fmaxf(s[u][0], s[u][1]));
                pmax1 = fmaxf(pmax1, fmaxf(s[u][2], s[u][3]));
            }
            pmax0 = fmaxf(pmax0, __shfl_xor_sync(0xffffffffu, pmax0, 1));
            pmax0 = fmaxf(pmax0, __shfl_xor_sync(0xffffffffu, pmax0, 2));
            pmax1 = fmaxf(pmax1, __shfl_xor_sync(0xffffffffu, pmax1, 1));
            pmax1 = fmaxf(pmax1, __shfl_xor_sync(0xffffffffu, pmax1, 2));
            if (tg == 0) {
                pm[wn * QTILE + r0] = pmax0;
                pm[wn * QTILE + r1] = pmax1;
            }
        }
        __syncthreads();

        // ---- phase B: combine maxes, exp in regs, store P + partial sums ----
        {
            float m0o = m_s[r0], m1o = m_s[r1];
            float m0n = fmaxf(fmaxf(m0o, fmaxf(pm[r0], pm[QTILE + r0])),
                              fmaxf(pm[2 * QTILE + r0], pm[3 * QTILE + r0]));
            float m1n = fmaxf(fmaxf(m1o, fmaxf(pm[r1], pm[QTILE + r1])),
                              fmaxf(pm[2 * QTILE + r1], pm[3 * QTILE + r1]));
            float sum0 = 0.0f, sum1 = 0.0f;
#pragma unroll
            for (int u = 0; u < 2; u++) {
                s[u][0] = f2tf32f(__expf(s[u][0] - m0n));
                s[u][1] = f2tf32f(__expf(s[u][1] - m0n));
                s[u][2] = f2tf32f(__expf(s[u][2] - m1n));
                s[u][3] = f2tf32f(__expf(s[u][3] - m1n));
                sum0 += s[u][0] + s[u][1];
                sum1 += s[u][2] + s[u][3];
            }
            sum0 += __shfl_xor_sync(0xffffffffu, sum0, 1);
            sum0 += __shfl_xor_sync(0xffffffffu, sum0, 2);
            sum1 += __shfl_xor_sync(0xffffffffu, sum1, 1);
            sum1 += __shfl_xor_sync(0xffffffffu, sum1, 2);
            const int ncol0 = wn * 16 + 2 * tg;
#pragma unroll
            for (int u = 0; u < 2; u++) {
                *(float2*)(ss + r0 * SS_ST + ncol0 + u * 8) = make_float2(s[u][0], s[u][1]);
                *(float2*)(ss + r1 * SS_ST + ncol0 + u * 8) = make_float2(s[u][2], s[u][3]);
            }
            if (tg == 0) {
                ps[wn * QTILE + r0] = sum0;
                ps[wn * QTILE + r1] = sum1;
            }
            if (wn == 0 && tg == 0) {
                f_s[r0] = __expf(m0o - m0n);
                f_s[r1] = __expf(m1o - m1n);
                mn_s[r0] = m0n;
                mn_s[r1] = m1n;
            }
        }
        __syncthreads();

        // ---- phase C: l/m update (designated), rescale O, P @ V ----
        if (wn == 0 && tg == 0) {
            l_s[r0] = l_s[r0] * f_s[r0] + ps[r0] + ps[QTILE + r0] + ps[2 * QTILE + r0] + ps[3 * QTILE + r0];
            l_s[r1] = l_s[r1] * f_s[r1] + ps[r1] + ps[QTILE + r1] + ps[2 * QTILE + r1] + ps[3 * QTILE + r1];
            m_s[r0] = mn_s[r0];
            m_s[r1] = mn_s[r1];
        }
        {
            float f0 = f_s[r0];
            float f1 = f_s[r1];
#pragma unroll
            for (int u = 0; u < 4; u++) {
                o[u][0] *= f0; o[u][1] *= f0;
                o[u][2] *= f1; o[u][3] *= f1;
            }
            const uint32_t* ssu = (const uint32_t*)ss;
            const uint32_t* vsu = (const uint32_t*)vs;
            const int dim0 = wn * 32;
#pragma unroll
            for (int kb = 0; kb < 8; kb++) {
                const int kc = kb * 8 + tg;
                uint32_t a[4];
                a[0] = ssu[r0 * SS_ST + kc];
                a[1] = ssu[r1 * SS_ST + kc];
                a[2] = ssu[r0 * SS_ST + kc + 4];
                a[3] = ssu[r1 * SS_ST + kc + 4];
#pragma unroll
                for (int u = 0; u < 4; u++) {
                    uint32_t bfr2[2];
                    int dcol = dim0 + u * 8 + g;
                    bfr2[0] = vsu[kc * VS_ST + dcol];
                    bfr2[1] = vsu[(kc + 4) * VS_ST + dcol];
                    MMA_TF32(o[u], a, bfr2);
                }
            }
        }
        __syncthreads();
    }

    // ---- epilogue ----
    {
        float linv0 = 1.0f / l_s[r0];
        float linv1 = 1.0f / l_s[r1];
        float* ob0 = O + (size_t)(b * SEQ + q0 + r0) * HIDDEN + h * HEAD_DIM + wn * 32 + 2 * tg;
        float* ob1 = O + (size_t)(b * SEQ + q0 + r1) * HIDDEN + h * HEAD_DIM + wn * 32 + 2 * tg;
#pragma unroll
        for (int u = 0; u < 4; u++) {
            *(float2*)(ob0 + u * 8) = make_float2(o[u][0] * linv0, o[u][1] * linv0);
            *(float2*)(ob1 + u * 8) = make_float2(o[u][2] * linv1, o[u][3] * linv1);
        }
    }
}

// ---------------- launch ----------------
extern "C" void kernel_launch(void* const* d_in, const int* in_sizes, int n_in,
                              void* d_out, int out_size) {
    (void)in_sizes; (void)n_in; (void)out_size;
    const float* x  = (const float*)d_in[0];
    const float* wq = (const float*)d_in[1];
    const float* wk = (const float*)d_in[2];
    const float* wv = (const float*)d_in[3];
    const float* wo = (const float*)d_in[4];
    float* out = (float*)d_out;

    float *qb, *kb, *vb, *ab;
    cudaGetSymbolAddress((void**)&qb, g_q);
    cudaGetSymbolAddress((void**)&kb, g_k);
    cudaGetSymbolAddress((void**)&vb, g_v);
    cudaGetSymbolAddress((void**)&ab, g_att);

    static int configured = 0;
    if (!configured) {
        cudaFuncSetAttribute(attn_kernel, cudaFuncAttributeMaxDynamicSharedMemorySize,
                             A_SMEM);
        cudaFuncSetAttribute(gemm_mma, cudaFuncAttributeMaxDynamicSharedMemorySize,
                             G_SMEM);
        cudaFuncSetAttribute(gemm_qkv, cudaFuncAttributeMaxDynamicSharedMemorySize,
                             G_SMEM);
        configured = 1;
    }

    gemm_qkv<<<dim3(18, MROWS / BM), 256, G_SMEM>>>(x, wq, wk, wv, qb, kb, vb);
    attn_kernel<<<dim3(SEQ / QTILE, HEADS, BATCH), 1024, A_SMEM>>>(qb, kb, vb, ab);
    gemm_mma<<<dim3(HIDDEN / BN, MROWS / BM), 256, G_SMEM>>>(ab, wo, out, MROWS, HIDDEN, HIDDEN);
}

// round 17
// speedup vs baseline: 1.1162x; 1.1162x over previous
#include <cuda_runtime.h>
#include <cstdint>

#define HIDDEN 2048
#define HEADS 16
#define HEAD_DIM 128
#define BATCH 2
#define SEQ 2048
#define MROWS (BATCH * SEQ)  // 4096

// ---------------- scratch (no allocations allowed) ----------------
__device__ float g_q[MROWS * HIDDEN];     // 32 MB
__device__ float g_k[MROWS * HEAD_DIM];   // 2 MB
__device__ float g_v[MROWS * HEAD_DIM];   // 2 MB
__device__ float g_att[MROWS * HIDDEN];   // 32 MB

__device__ __forceinline__ uint32_t f2tf32(float x) {
    uint32_t r;
    asm("cvt.rna.tf32.f32 %0, %1;" : "=r"(r) : "f"(x));
    return r;
}
__device__ __forceinline__ float f2tf32f(float x) {
    return __uint_as_float(f2tf32(x));
}

#define MMA_TF32(d, a, b)                                                          \
    asm volatile(                                                                  \
        "mma.sync.aligned.m16n8k8.row.col.f32.tf32.tf32.f32 "                      \
        "{%0,%1,%2,%3}, {%4,%5,%6,%7}, {%8,%9}, {%0,%1,%2,%3};"                    \
        : "+f"((d)[0]), "+f"((d)[1]), "+f"((d)[2]), "+f"((d)[3])                   \
        : "r"((a)[0]), "r"((a)[1]), "r"((a)[2]), "r"((a)[3]),                      \
          "r"((b)[0]), "r"((b)[1]))

// ---------------- shared GEMM tile params ----------------
#define BM 128
#define BN 128
#define BK 32
#define SA 36
#define BUF_WORDS (BM * SA)
#define G_SMEM (2 * 2 * BUF_WORDS * 4)

// ---- core tf32 GEMM body: C[M,N] = A[M,K] @ B[N,K]^T (tile at m0,n0) ----
__device__ __forceinline__ void gemm_body(const float* __restrict__ A,
                                          const float* __restrict__ B,
                                          float* __restrict__ C,
                                          int K, int Cn, int m0, int n0,
                                          float* sm) {
    const int tid = threadIdx.x;
    const int w = tid >> 5;
    const int lane = tid & 31;
    const int g = lane >> 2;
    const int tg = lane & 3;
    const int warp_m = (w & 3) * 32;
    const int warp_n = (w >> 2) * 64;

    float acc[2][8][4];
#pragma unroll
    for (int t = 0; t < 2; t++)
#pragma unroll
        for (int u = 0; u < 8; u++)
#pragma unroll
            for (int j = 0; j < 4; j++) acc[t][u][j] = 0.0f;

    const int steps = K / BK;
    const int r_ld = tid >> 3;
    const int c_ld = (tid & 7) * 4;

    float4 afr[4], bfr[4];

    auto ldg = [&](int s) {
        const int k0 = s * BK;
#pragma unroll
        for (int i = 0; i < 4; i++) {
            int r = r_ld + i * 32;
            afr[i] = *(const float4*)(A + (size_t)(m0 + r) * K + k0 + c_ld);
            bfr[i] = *(const float4*)(B + (size_t)(n0 + r) * K + k0 + c_ld);
        }
    };
    auto sts = [&](int buf) {
        float* As = sm + buf * (2 * BUF_WORDS);
        float* Bs = As + BUF_WORDS;
#pragma unroll
        for (int i = 0; i < 4; i++) {
            int r = r_ld + i * 32;
            uint4 u;
            u.x = f2tf32(afr[i].x); u.y = f2tf32(afr[i].y);
            u.z = f2tf32(afr[i].z); u.w = f2tf32(afr[i].w);
            *(uint4*)(As + r * SA + c_ld) = u;
            u.x = f2tf32(bfr[i].x); u.y = f2tf32(bfr[i].y);
            u.z = f2tf32(bfr[i].z); u.w = f2tf32(bfr[i].w);
            *(uint4*)(Bs + r * SA + c_ld) = u;
        }
    };
    auto compute = [&](int buf) {
        const uint32_t* As = (const uint32_t*)(sm + buf * (2 * BUF_WORDS));
        const uint32_t* Bs = As + BUF_WORDS;
#pragma unroll
        for (int ks = 0; ks < 4; ks++) {
            const int kc = ks * 8 + tg;
            uint32_t a[2][4];
#pragma unroll
            for (int t = 0; t < 2; t++) {
                int row = warp_m + t * 16 + g;
                a[t][0] = As[row * SA + kc];
                a[t][1] = As[(row + 8) * SA + kc];
                a[t][2] = As[row * SA + kc + 4];
                a[t][3] = As[(row + 8) * SA + kc + 4];
            }
            uint32_t b[8][2];
#pragma unroll
            for (int u = 0; u < 8; u++) {
                int row = warp_n + u * 8 + g;
                b[u][0] = Bs[row * SA + kc];
                b[u][1] = Bs[row * SA + kc + 4];
            }
#pragma unroll
            for (int t = 0; t < 2; t++)
#pragma unroll
                for (int u = 0; u < 8; u++)
                    MMA_TF32(acc[t][u], a[t], b[u]);
        }
    };

    ldg(0);
    sts(0);
    __syncthreads();

    for (int s = 0; s < steps; s++) {
        const int cur = s & 1;
        if (s + 1 < steps) ldg(s + 1);
        compute(cur);
        if (s + 1 < steps) sts(cur ^ 1);
        __syncthreads();
    }

#pragma unroll
    for (int t = 0; t < 2; t++) {
        int r0 = m0 + warp_m + t * 16 + g;
#pragma unroll
        for (int u = 0; u < 8; u++) {
            int col = n0 + warp_n + u * 8 + 2 * tg;
            *(float2*)(C + (size_t)r0 * Cn + col) = make_float2(acc[t][u][0], acc[t][u][1]);
            *(float2*)(C + (size_t)(r0 + 8) * Cn + col) = make_float2(acc[t][u][2], acc[t][u][3]);
        }
    }
}

// out-projection GEMM (generic); request 2 CTAs/SM (regs <= 128)
__global__ void __launch_bounds__(256, 2) gemm_mma(const float* __restrict__ A,
                                                   const float* __restrict__ B,
                                                   float* __restrict__ C,
                                                   int M, int N, int K) {
    extern __shared__ float sm[];
    gemm_body(A, B, C, K, N, blockIdx.y * BM, blockIdx.x * BN, sm);
}

// fused Q/K/V projection: grid.x 0..15 -> wq tiles, 16 -> wk, 17 -> wv
__global__ void __launch_bounds__(256, 2) gemm_qkv(const float* __restrict__ x,
                                                   const float* __restrict__ wq,
                                                   const float* __restrict__ wk,
                                                   const float* __restrict__ wv,
                                                   float* __restrict__ qo,
                                                   float* __restrict__ ko,
                                                   float* __restrict__ vo) {
    extern __shared__ float sm[];
    const int bx = blockIdx.x;
    const float* B;
    float* C;
    int Cn, n0;
    if (bx < 16)      { B = wq; C = qo; Cn = HIDDEN;   n0 = bx * BN; }
    else if (bx == 16){ B = wk; C = ko; Cn = HEAD_DIM; n0 = 0; }
    else              { B = wv; C = vo; Cn = HEAD_DIM; n0 = 0; }
    gemm_body(x, B, C, HIDDEN, Cn, blockIdx.y * BM, n0, sm);
}

// ---------------- Flash attention v5 (R13 winner): register softmax ----------------
// 128q/CTA, 64-key tiles, 512 threads (16 warps). QK warp = 16x32 (wm 0..7, wn 0..1).
// Scores stay in registers; row-max/sum via quad shfl + cross-warp partials.
#define QTILE 128
#define QS_ST 132
#define KS_ST 132
#define VS_ST 136
#define SS_ST 68
#define OFF_QS 0
#define OFF_KS (QTILE * QS_ST)                  // 16896
#define OFF_VS (OFF_KS + 64 * KS_ST)            // 25344
#define OFF_SS (OFF_VS + 64 * VS_ST)            // 34048
#define OFF_M  (OFF_SS + QTILE * SS_ST)         // 42752
#define OFF_L  (OFF_M + QTILE)
#define OFF_F  (OFF_L + QTILE)
#define OFF_MN (OFF_F + QTILE)
#define OFF_PM (OFF_MN + QTILE)                 // [2][128]
#define OFF_PS (OFF_PM + 2 * QTILE)             // [2][128]
#define A_SMEM ((OFF_PS + 2 * QTILE) * 4)       // 175104 bytes

__global__ void __launch_bounds__(512, 1) attn_kernel(const float* __restrict__ Q,
                                                      const float* __restrict__ Km,
                                                      const float* __restrict__ Vm,
                                                      float* __restrict__ O) {
    const int b = blockIdx.z;
    const int h = blockIdx.y;
    const int q0 = blockIdx.x * QTILE;

    extern __shared__ float sm[];
    float* qs   = sm + OFF_QS;
    float* ks   = sm + OFF_KS;
    float* vs   = sm + OFF_VS;
    float* ss   = sm + OFF_SS;
    float* m_s  = sm + OFF_M;
    float* l_s  = sm + OFF_L;
    float* f_s  = sm + OFF_F;
    float* mn_s = sm + OFF_MN;
    float* pm   = sm + OFF_PM;
    float* ps   = sm + OFF_PS;

    const int tid = threadIdx.x;
    const int w = tid >> 5;
    const int lane = tid & 31;
    const int g = lane >> 2;
    const int tg = lane & 3;
    const int wm = w & 7;          // 0..7: rows wm*16..+15
    const int wn = w >> 3;         // 0..1
    const float inv_norm = 0.08838834764831845f;  // 1/sqrt(128)

    const int r_st = tid >> 5;     // 0..15
    const int c_st = lane * 4;     // float col 0..124
    const int r0 = wm * 16 + g;
    const int r1 = r0 + 8;

    // ---- stage Q (128x128, tf32, stride 132) ----
    {
        const float* qbase = Q + (size_t)(b * SEQ + q0) * HIDDEN + h * HEAD_DIM;
#pragma unroll
        for (int it = 0; it < 8; it++) {
            int r = r_st + it * 16;
            float4 v = *(const float4*)(qbase + (size_t)r * HIDDEN + c_st);
            float* d = qs + r * QS_ST + c_st;
            d[0] = f2tf32f(v.x); d[1] = f2tf32f(v.y);
            d[2] = f2tf32f(v.z); d[3] = f2tf32f(v.w);
        }
    }
    if (tid < QTILE) {
        m_s[tid] = -3.0e38f;
        l_s[tid] = 0.0f;
    }

    float o[8][4];
#pragma unroll
    for (int u = 0; u < 8; u++)
#pragma unroll
        for (int j = 0; j < 4; j++) o[u][j] = 0.0f;

    __syncthreads();

    for (int t0 = 0; t0 < SEQ; t0 += 64) {
        // ---- stage K (stride 132) and V (stride 136), tf32 ----
        {
            const float* kbase = Km + (size_t)(b * SEQ + t0) * HEAD_DIM;
            const float* vbase = Vm + (size_t)(b * SEQ + t0) * HEAD_DIM;
#pragma unroll
            for (int it = 0; it < 4; it++) {
                int r = r_st + it * 16;
                float4 kv = *(const float4*)(kbase + (size_t)r * HEAD_DIM + c_st);
                float* dk = ks + r * KS_ST + c_st;
                dk[0] = f2tf32f(kv.x); dk[1] = f2tf32f(kv.y);
                dk[2] = f2tf32f(kv.z); dk[3] = f2tf32f(kv.w);
                float4 vv = *(const float4*)(vbase + (size_t)r * HEAD_DIM + c_st);
                float* dv = vs + r * VS_ST + c_st;
                dv[0] = f2tf32f(vv.x); dv[1] = f2tf32f(vv.y);
                dv[2] = f2tf32f(vv.z); dv[3] = f2tf32f(vv.w);
            }
        }
        __syncthreads();

        // ---- QK^T: warp computes S[wm*16..+15][wn*32..+31] (regs) ----
        float s[4][4];
#pragma unroll
        for (int u = 0; u < 4; u++)
#pragma unroll
            for (int j = 0; j < 4; j++) s[u][j] = 0.0f;
        {
            const uint32_t* qsu = (const uint32_t*)qs;
            const uint32_t* ksu = (const uint32_t*)ks;
            const int ncol0 = wn * 32;
#pragma unroll
            for (int kb = 0; kb < 16; kb++) {
                const int kc = kb * 8 + tg;
                uint32_t a[4];
                a[0] = qsu[r0 * QS_ST + kc];
                a[1] = qsu[r1 * QS_ST + kc];
                a[2] = qsu[r0 * QS_ST + kc + 4];
                a[3] = qsu[r1 * QS_ST + kc + 4];
#pragma unroll
                for (int u = 0; u < 4; u++) {
                    uint32_t bfr2[2];
                    int krow = ncol0 + u * 8 + g;
                    bfr2[0] = ksu[krow * KS_ST + kc];
                    bfr2[1] = ksu[krow * KS_ST + kc + 4];
                    MMA_TF32(s[u], a, bfr2);
                }
            }
        }

        // ---- register softmax, phase A: scale + partial row max (quad) ----
        float pmax0 = -3.0e38f, pmax1 = -3.0e38f;
#pragma unroll
        for (int u = 0; u < 4; u++) {
            s[u][0] *= inv_norm; s[u][1] *= inv_norm;
            s[u][2] *= inv_norm; s[u][3] *= inv_norm;
            pmax0 = fmaxf(pmax0, fmaxf(s[u][0], s[u][1]));
            pmax1 = fmaxf(pmax1, fmaxf(s[u][2], s[u][3]));
        }
        pmax0 = fmaxf(pmax0, __shfl_xor_sync(0xffffffffu, pmax0, 1));
        pmax0 = fmaxf(pmax0, __shfl_xor_sync(0xffffffffu, pmax0, 2));
        pmax1 = fmaxf(pmax1, __shfl_xor_sync(0xffffffffu, pmax1, 1));
        pmax1 = fmaxf(pmax1, __shfl_xor_sync(0xffffffffu, pmax1, 2));
        if (tg == 0) {
            pm[wn * QTILE + r0] = pmax0;
            pm[wn * QTILE + r1] = pmax1;
        }
        __syncthreads();

        // ---- phase B: combine maxes, exp in regs, store P + partial sums ----
        {
            float m0o = m_s[r0], m1o = m_s[r1];
            float m0n = fmaxf(m0o, fmaxf(pm[r0], pm[QTILE + r0]));
            float m1n = fmaxf(m1o, fmaxf(pm[r1], pm[QTILE + r1]));
            float sum0 = 0.0f, sum1 = 0.0f;
#pragma unroll
            for (int u = 0; u < 4; u++) {
                s[u][0] = f2tf32f(__expf(s[u][0] - m0n));
                s[u][1] = f2tf32f(__expf(s[u][1] - m0n));
                s[u][2] = f2tf32f(__expf(s[u][2] - m1n));
                s[u][3] = f2tf32f(__expf(s[u][3] - m1n));
                sum0 += s[u][0] + s[u][1];
                sum1 += s[u][2] + s[u][3];
            }
            sum0 += __shfl_xor_sync(0xffffffffu, sum0, 1);
            sum0 += __shfl_xor_sync(0xffffffffu, sum0, 2);
            sum1 += __shfl_xor_sync(0xffffffffu, sum1, 1);
            sum1 += __shfl_xor_sync(0xffffffffu, sum1, 2);
            const int ncol0 = wn * 32 + 2 * tg;
#pragma unroll
            for (int u = 0; u < 4; u++) {
                *(float2*)(ss + r0 * SS_ST + ncol0 + u * 8) = make_float2(s[u][0], s[u][1]);
                *(float2*)(ss + r1 * SS_ST + ncol0 + u * 8) = make_float2(s[u][2], s[u][3]);
            }
            if (tg == 0) {
                ps[wn * QTILE + r0] = sum0;
                ps[wn * QTILE + r1] = sum1;
            }
            if (wn == 0 && tg == 0) {
                f_s[r0] = __expf(m0o - m0n);
                f_s[r1] = __expf(m1o - m1n);
                mn_s[r0] = m0n;
                mn_s[r1] = m1n;
            }
        }
        __syncthreads();

        // ---- phase C: l/m update (designated), rescale O, P @ V ----
        if (wn == 0 && tg == 0) {
            l_s[r0] = l_s[r0] * f_s[r0] + ps[r0] + ps[QTILE + r0];
            l_s[r1] = l_s[r1] * f_s[r1] + ps[r1] + ps[QTILE + r1];
            m_s[r0] = mn_s[r0];
            m_s[r1] = mn_s[r1];
        }
        {
            float f0 = f_s[r0];
            float f1 = f_s[r1];
#pragma unroll
            for (int u = 0; u < 8; u++) {
                o[u][0] *= f0; o[u][1] *= f0;
                o[u][2] *= f1; o[u][3] *= f1;
            }
            const uint32_t* ssu = (const uint32_t*)ss;
            const uint32_t* vsu = (const uint32_t*)vs;
            const int dim0 = wn * 64;
#pragma unroll
            for (int kb = 0; kb < 8; kb++) {
                const int kc = kb * 8 + tg;
                uint32_t a[4];
                a[0] = ssu[r0 * SS_ST + kc];
                a[1] = ssu[r1 * SS_ST + kc];
                a[2] = ssu[r0 * SS_ST + kc + 4];
                a[3] = ssu[r1 * SS_ST + kc + 4];
#pragma unroll
                for (int u = 0; u < 8; u++) {
                    uint32_t bfr2[2];
                    int dcol = dim0 + u * 8 + g;
                    bfr2[0] = vsu[kc * VS_ST + dcol];
                    bfr2[1] = vsu[(kc + 4) * VS_ST + dcol];
                    MMA_TF32(o[u], a, bfr2);
                }
            }
        }
        __syncthreads();
    }

    // ---- epilogue ----
    {
        float linv0 = 1.0f / l_s[r0];
        float linv1 = 1.0f / l_s[r1];
        float* ob0 = O + (size_t)(b * SEQ + q0 + r0) * HIDDEN + h * HEAD_DIM + wn * 64 + 2 * tg;
        float* ob1 = O + (size_t)(b * SEQ + q0 + r1) * HIDDEN + h * HEAD_DIM + wn * 64 + 2 * tg;
#pragma unroll
        for (int u = 0; u < 8; u++) {
            *(float2*)(ob0 + u * 8) = make_float2(o[u][0] * linv0, o[u][1] * linv0);
            *(float2*)(ob1 + u * 8) = make_float2(o[u][2] * linv1, o[u][3] * linv1);
        }
    }
}

// ---------------- launch ----------------
extern "C" void kernel_launch(void* const* d_in, const int* in_sizes, int n_in,
                              void* d_out, int out_size) {
    (void)in_sizes; (void)n_in; (void)out_size;
    const float* x  = (const float*)d_in[0];
    const float* wq = (const float*)d_in[1];
    const float* wk = (const float*)d_in[2];
    const float* wv = (const float*)d_in[3];
    const float* wo = (const float*)d_in[4];
    float* out = (float*)d_out;

    float *qb, *kb, *vb, *ab;
    cudaGetSymbolAddress((void**)&qb, g_q);
    cudaGetSymbolAddress((void**)&kb, g_k);
    cudaGetSymbolAddress((void**)&vb, g_v);
    cudaGetSymbolAddress((void**)&ab, g_att);

    static int configured = 0;
    if (!configured) {
        cudaFuncSetAttribute(attn_kernel, cudaFuncAttributeMaxDynamicSharedMemorySize,
                             A_SMEM);
        cudaFuncSetAttribute(gemm_mma, cudaFuncAttributeMaxDynamicSharedMemorySize,
                             G_SMEM);
        cudaFuncSetAttribute(gemm_qkv, cudaFuncAttributeMaxDynamicSharedMemorySize,
                             G_SMEM);
        configured = 1;
    }

    gemm_qkv<<<dim3(18, MROWS / BM), 256, G_SMEM>>>(x, wq, wk, wv, qb, kb, vb);
    attn_kernel<<<dim3(SEQ / QTILE, HEADS, BATCH), 512, A_SMEM>>>(qb, kb, vb, ab);
    gemm_mma<<<dim3(HIDDEN / BN, MROWS / BM), 256, G_SMEM>>>(ab, wo, out, MROWS, HIDDEN, HIDDEN);
}